// round 8
// baseline (speedup 1.0000x reference)
#include <cuda_runtime.h>
#include <math.h>

#define STEPS 2048
#define BATCH 512
#define SPB   2
#define NBLK  (BATCH / SPB)   // 256 blocks, 2 per SM -> one wave
#define THREADS 256

typedef unsigned long long u64;

__device__ float g_baseflow[BATCH];

// ---------------------------------------------------------------------------
__device__ __forceinline__ u64 pack2(float lo, float hi) {
    u64 r; asm("mov.b64 %0, {%1, %2};" : "=l"(r) : "f"(lo), "f"(hi)); return r;
}
__device__ __forceinline__ void fma2(u64& acc, u64 a, u64 b) {
    asm("fma.rn.f32x2 %0, %1, %2, %0;" : "+l"(acc) : "l"(a), "l"(b));
}
__device__ __forceinline__ float fast_sigmoid(float v) {
    return __fdividef(1.0f, 1.0f + __expf(-v));
}

// ---------------------------------------------------------------------------
// Kernel 1: per-batch-element 25th percentile of flow (bitonic sort)
// ---------------------------------------------------------------------------
__global__ void baseflow_kernel(const float* __restrict__ hyd) {
    __shared__ float v[STEPS];
    const int b = blockIdx.x;
    const int tid = threadIdx.x;
    for (int t = tid; t < STEPS; t += blockDim.x)
        v[t] = hyd[(t * BATCH + b) * 17];
    __syncthreads();
    for (int k = 2; k <= STEPS; k <<= 1) {
        for (int j = k >> 1; j > 0; j >>= 1) {
            for (int i = tid; i < STEPS; i += blockDim.x) {
                int l = i ^ j;
                if (l > i) {
                    float a = v[i], c = v[l];
                    bool up = ((i & k) == 0);
                    if ((a > c) == up) { v[i] = c; v[l] = a; }
                }
            }
            __syncthreads();
        }
    }
    if (tid == 0)
        g_baseflow[b] = 0.25f * v[511] + 0.75f * v[512];   // pos = 511.75
}

// ---------------------------------------------------------------------------
// SMEM layout (~63 KB -> two CTAs fit per SM)
// ---------------------------------------------------------------------------
struct __align__(16) Smem {
    float wct[128 * 96];     // 48KB  combined [W_in;W_out] transposed [k][j], j<89 valid
    float w0t[16 * 128];     // W0 x-part transposed [i][j]
    float w0sp[8 * 128];     // 0.01 * W0 stores-part [k][j]
    float b0s[128];
    float b1s[128];
    float bcs[96];
    float xin[16 * 2];       // staged x_{t+1} [i][s]
    float l0p[128 * 2];      // layer0-x partial incl b0 [j][s]
    float hA[128 * 2];       // layer0 out [j][s]
    float hB[128 * 2];       // layer1 out
    float part1[4][128][2];  // layer1 partials [q][j][s]
    float part2[2][96][2];   // layer2 partials [q][j][s]
    float outg[2][80];       // sigmoided gates [s][col]
    float st[2 * 8];         // stores broadcast
    float bflow_s[2];
};

// ---------------------------------------------------------------------------
// 256 threads = 8 warps; 2 samples per block; 2 blocks co-resident per SM.
// Layer1: thread owns units (u6, u6+64), k-slice q4 = tid>>6 (4-way), W1 regs.
// Layer2: threads 0..177 (warps 0-5): unit t%89, k-half t/89, weights in SMEM.
//         warps 6-7: l0x(t+1) (2 units/thread).
// Epilogue: warps 0,1 (one sample each). hA-finish: all 256.
// ---------------------------------------------------------------------------
__global__ void __launch_bounds__(THREADS, 2)
hyd_kernel(const float* __restrict__ hyd,
           const float* __restrict__ W0, const float* __restrict__ b0,
           const float* __restrict__ W1, const float* __restrict__ b1,
           const float* __restrict__ Wi, const float* __restrict__ bi,
           const float* __restrict__ Wo, const float* __restrict__ bo,
           float* __restrict__ out)
{
    extern __shared__ char raw[];
    Smem& S = *(Smem*)raw;
    const int tid   = threadIdx.x;
    const int lane  = tid & 31;
    const int wwarp = tid >> 5;          // 0..7
    const int u6    = tid & 63;
    const int q4    = tid >> 6;          // 0..3
    const int blk   = blockIdx.x;

    // ---- register-resident W1 slices: units u6 and u6+64, k in [32*q4, +32) ----
    float w1a[32], w1b[32];
    #pragma unroll
    for (int k = 0; k < 32; k++) {
        w1a[k] = W1[u6 * 128 + q4 * 32 + k];
        w1b[k] = W1[(u6 + 64) * 128 + q4 * 32 + k];
    }

    // ---- SMEM init ----
    for (int idx = tid; idx < 128 * 96; idx += THREADS) {
        int k = idx / 96, j = idx % 96;
        float v = 0.f;
        if (j < 9)       v = Wi[j * 128 + k];
        else if (j < 89) v = Wo[(j - 9) * 128 + k];
        S.wct[idx] = v;
    }
    for (int idx = tid; idx < 16 * 128; idx += THREADS) {
        int i = idx >> 7, jj = idx & 127;
        S.w0t[idx] = W0[jj * 24 + i];
    }
    for (int idx = tid; idx < 8 * 128; idx += THREADS) {
        int k = idx >> 7, jj = idx & 127;
        S.w0sp[idx] = 0.01f * W0[jj * 24 + 16 + k];
    }
    if (tid < 128) { S.b0s[tid] = b0[tid]; S.b1s[tid] = b1[tid]; }
    if (tid < 96)  S.bcs[tid] = (tid < 9) ? bi[tid] : (tid < 89 ? bo[tid - 9] : 0.f);
    if (tid < 16)  S.st[tid] = ((tid & 7) == 1) ? 1.0f : 0.0f;
    if (tid < SPB) S.bflow_s[tid] = g_baseflow[blk * SPB + tid];

    // per-warp roles
    const int bsample = blk * SPB + wwarp;          // warps 0,1: epilogue sample
    const int xsample = blk * SPB + (wwarp - 2);    // warps 2,3: x prefetch
    float rain_cur = 0.f, rain_next = 0.f, xreg = 0.f;

    if (wwarp < 2 && lane == 0)
        rain_cur = hyd[bsample * 17 + 1];
    if (wwarp >= 2 && wwarp < 4 && lane < 16)
        S.xin[lane * 2 + (wwarp - 2)] = hyd[xsample * 17 + 1 + lane];
    __syncthreads();

    // ---- bootstrap: l0p(0) then hA(0) ----
    {
        int jj = tid >> 1, s = tid & 1;
        float v = S.b0s[jj];
        #pragma unroll
        for (int i = 0; i < 16; i++)
            v = fmaf(S.w0t[i * 128 + jj], S.xin[i * 2 + s], v);
        S.l0p[jj * 2 + s] = v;
    }
    __syncthreads();
    {
        int jj = tid >> 1, s = tid & 1;
        float v = S.l0p[jj * 2 + s];
        #pragma unroll
        for (int k = 0; k < 8; k++)
            v = fmaf(S.w0sp[k * 128 + jj], S.st[s * 8 + k], v);
        S.hA[jj * 2 + s] = fmaxf(v, 0.f);
    }
    __syncthreads();

    // persistent stores in lane 0 of warps 0,1
    float sv[8];
    #pragma unroll
    for (int k = 0; k < 8; k++) sv[k] = (k == 1) ? 1.0f : 0.0f;

    // layer2 role (warps 0-5)
    const int t2   = tid;
    const int j2   = (t2 < 178) ? (t2 % 89) : 0;
    const int q2   = (t2 < 178) ? (t2 / 89) : 0;

    for (int t = 0; t < STEPS; t++) {
        // ======== S1: layer1 partials (units u6, u6+64; slice q4) ========
        {
            float ba = (q4 == 0) ? S.b1s[u6] : 0.f;
            float bb_ = (q4 == 0) ? S.b1s[u6 + 64] : 0.f;
            u64 aa = pack2(ba, ba), ab = pack2(bb_, bb_);
            const float* hp = &S.hA[q4 * 32 * 2];
            #pragma unroll
            for (int k = 0; k < 32; k++) {
                u64 h = *(const u64*)&hp[k * 2];
                fma2(aa, h, pack2(w1a[k], w1a[k]));
                fma2(ab, h, pack2(w1b[k], w1b[k]));
            }
            *(u64*)&S.part1[q4][u6][0]      = aa;
            *(u64*)&S.part1[q4][u6 + 64][0] = ab;
        }
        // prefetch x_{t+1} / rain_{t+1}
        if (t + 1 < STEPS) {
            if (wwarp < 2 && lane == 0)
                rain_next = hyd[((t + 1) * BATCH + bsample) * 17 + 1];
            if (wwarp >= 2 && wwarp < 4 && lane < 16)
                xreg = hyd[((t + 1) * BATCH + xsample) * 17 + 1 + lane];
        }
        __syncthreads();

        // ======== S2: combine1 -> hB ; stage x_{t+1} ========
        {
            int jj = tid >> 1, s = tid & 1;
            float v = S.part1[0][jj][s] + S.part1[1][jj][s]
                    + S.part1[2][jj][s] + S.part1[3][jj][s];
            S.hB[jj * 2 + s] = fmaxf(v, 0.f);
        }
        if (wwarp >= 2 && wwarp < 4 && lane < 16)
            S.xin[lane * 2 + (wwarp - 2)] = xreg;
        __syncthreads();

        // ======== S3: layer2 (warps 0-5) || l0x(t+1) (warps 6-7) ========
        if (wwarp >= 6) {
            // 64 threads, 2 units each: u and u+64
            int u = tid - 192;
            float b0a = S.b0s[u], b0b = S.b0s[u + 64];
            u64 aa = pack2(b0a, b0a), ab = pack2(b0b, b0b);
            #pragma unroll
            for (int i = 0; i < 16; i++) {
                u64 h = *(const u64*)&S.xin[i * 2];
                fma2(aa, h, pack2(S.w0t[i * 128 + u], S.w0t[i * 128 + u]));
                fma2(ab, h, pack2(S.w0t[i * 128 + u + 64], S.w0t[i * 128 + u + 64]));
            }
            *(u64*)&S.l0p[u * 2]        = aa;
            *(u64*)&S.l0p[(u + 64) * 2] = ab;
        } else if (t2 < 178) {
            float bj = (q2 == 0) ? S.bcs[j2] : 0.f;
            u64 acc = pack2(bj, bj);
            const float* hp = &S.hB[q2 * 64 * 2];
            const float* wp = &S.wct[q2 * 64 * 96 + j2];
            #pragma unroll
            for (int k = 0; k < 64; k++) {
                float w = wp[k * 96];
                u64 h = *(const u64*)&hp[k * 2];
                fma2(acc, h, pack2(w, w));
            }
            *(u64*)&S.part2[q2][j2][0] = acc;
        }
        __syncthreads();

        // ======== S4: epilogue (warps 0,1; warp s = sample s) ========
        if (wwarp < 2) {
            const int s = wwarp;
            float v0 = S.part2[0][lane][s] + S.part2[1][lane][s];
            int j1 = lane + 32, jx = lane + 64;
            float v1 = S.part2[0][j1][s] + S.part2[1][j1][s];
            float v2 = 0.f;
            if (lane < 25)
                v2 = S.part2[0][jx][s] + S.part2[1][jx][s];

            // sigmoids spread across lanes
            if (lane >= 9) S.outg[s][lane - 9] = fast_sigmoid(v0);
            S.outg[s][lane + 23] = fast_sigmoid(v1);
            if (lane < 25) S.outg[s][lane + 55] = fast_sigmoid(v2);

            // gather 9 logits
            float lg[9];
            #pragma unroll
            for (int k = 0; k < 9; k++)
                lg[k] = __shfl_sync(0xffffffffu, v0, k);
            __syncwarp();

            if (lane == 0) {
                // softmax (tree max/sum)
                float m01 = fmaxf(lg[0], lg[1]), m23 = fmaxf(lg[2], lg[3]);
                float m45 = fmaxf(lg[4], lg[5]), m67 = fmaxf(lg[6], lg[7]);
                float m = fmaxf(fmaxf(fmaxf(m01, m23), fmaxf(m45, m67)), lg[8]);
                float e[9];
                #pragma unroll
                for (int k = 0; k < 9; k++) e[k] = __expf(lg[k] - m);
                float s01 = e[0] + e[1], s23 = e[2] + e[3];
                float s45 = e[4] + e[5], s67 = e[6] + e[7];
                float ssum = ((s01 + s23) + (s45 + s67)) + e[8];
                float r2 = __fdividef(rain_cur, ssum);
                #pragma unroll
                for (int k = 0; k < 8; k++) sv[k] += e[k + 1] * r2;

                const float* bb = S.outg[s];
                #pragma unroll
                for (int d = 0; d < 8; d++) {
                    float4 bv0 = *(const float4*)&bb[d * 8];
                    float4 bv1 = *(const float4*)&bb[d * 8 + 4];
                    float fb0 = bv0.x * sv[0], fb1 = bv0.y * sv[1];
                    float fb2 = bv0.z * sv[2], fb3 = bv0.w * sv[3];
                    float fb4 = bv1.x * sv[4], fb5 = bv1.y * sv[5];
                    float fb6 = bv1.z * sv[6], fb7 = bv1.w * sv[7];
                    float fsum = ((fb0 + fb1) + (fb2 + fb3))
                               + ((fb4 + fb5) + (fb6 + fb7));
                    sv[0] -= fb0; sv[1] -= fb1; sv[2] -= fb2; sv[3] -= fb3;
                    sv[4] -= fb4; sv[5] -= fb5; sv[6] -= fb6; sv[7] -= fb7;
                    sv[d] += fsum;
                }
                {   // escape
                    float4 e0 = *(const float4*)&bb[64];
                    float4 e1 = *(const float4*)&bb[68];
                    sv[0] -= e0.x * sv[0]; sv[1] -= e0.y * sv[1];
                    sv[2] -= e0.z * sv[2]; sv[3] -= e0.w * sv[3];
                    sv[4] -= e1.x * sv[4]; sv[5] -= e1.y * sv[5];
                    sv[6] -= e1.z * sv[6]; sv[7] -= e1.w * sv[7];
                }
                {   // flow
                    float4 f0 = *(const float4*)&bb[72];
                    float4 f1 = *(const float4*)&bb[76];
                    float fd0 = f0.x * sv[0], fd1 = f0.y * sv[1];
                    float fd2 = f0.z * sv[2], fd3 = f0.w * sv[3];
                    float fd4 = f1.x * sv[4], fd5 = f1.y * sv[5];
                    float fd6 = f1.z * sv[6], fd7 = f1.w * sv[7];
                    float flow = ((fd0 + fd1) + (fd2 + fd3))
                               + ((fd4 + fd5) + (fd6 + fd7));
                    sv[0] -= fd0; sv[1] -= fd1; sv[2] -= fd2; sv[3] -= fd3;
                    sv[4] -= fd4; sv[5] -= fd5; sv[6] -= fd6; sv[7] -= fd7;
                    out[t * BATCH + bsample] = flow;
                    if (t == 0)
                        sv[2] = S.bflow_s[s] / fmaxf(f0.z, 1e-5f);  // b_flow[SLOW]
                }
                #pragma unroll
                for (int k = 0; k < 8; k++) S.st[s * 8 + k] = sv[k];
                rain_cur = rain_next;
            }
        }
        __syncthreads();

        // ======== S5: hA(t+1) finish (all 256, one (j,s) each) ========
        {
            int jj = tid >> 1, s = tid & 1;
            float v = S.l0p[jj * 2 + s];
            #pragma unroll
            for (int k = 0; k < 8; k++)
                v = fmaf(S.w0sp[k * 128 + jj], S.st[s * 8 + k], v);
            S.hA[jj * 2 + s] = fmaxf(v, 0.f);
        }
        __syncthreads();
    }
}

// ---------------------------------------------------------------------------
// Harness entry.  Inputs: hyd_input, W0, b0, W1, b1, W_in, b_in, W_out, b_out
// ---------------------------------------------------------------------------
extern "C" void kernel_launch(void* const* d_in, const int* in_sizes, int n_in,
                              void* d_out, int out_size) {
    const float* hyd = (const float*)d_in[0];
    const float* W0  = (const float*)d_in[1];
    const float* b0  = (const float*)d_in[2];
    const float* W1  = (const float*)d_in[3];
    const float* b1  = (const float*)d_in[4];
    const float* Wi  = (const float*)d_in[5];
    const float* bi  = (const float*)d_in[6];
    const float* Wo  = (const float*)d_in[7];
    const float* bo  = (const float*)d_in[8];
    float* out = (float*)d_out;

    cudaFuncSetAttribute(hyd_kernel,
                         cudaFuncAttributeMaxDynamicSharedMemorySize,
                         (int)sizeof(Smem));

    baseflow_kernel<<<BATCH, 1024>>>(hyd);
    hyd_kernel<<<NBLK, THREADS, sizeof(Smem)>>>(hyd, W0, b0, W1, b1, Wi, bi, Wo, bo, out);
}